// round 1
// baseline (speedup 1.0000x reference)
#include <cuda_runtime.h>
#include <cuda_bf16.h>
#include <math.h>

// ---------------- problem constants ----------------
#define Bc 4
#define Sc 4096
#define Dc 1024
#define Hc 16
#define Dhc 64
#define Ec 256
#define Fc 4096
#define NBc 64
#define CHUNKc 128
#define Mrows (Bc * Sc)          // 16384
#define QKVW (3 * Hc * Dhc)      // 3072
#define NCHUNK (Sc / CHUNKc)     // 32

// ---------------- scratch (device globals; no allocations allowed) ----------------
__device__ float g_bufH[(size_t)Mrows * Dc];
__device__ float g_bufE[(size_t)Mrows * Ec];
__device__ float g_bufG[(size_t)Mrows * Dc];
__device__ float g_bufXA[(size_t)Mrows * Dc];
__device__ float g_bufQKV[(size_t)Mrows * QKVW];
__device__ float g_bufATT[(size_t)Mrows * Dc];
__device__ float g_bufT[(size_t)Mrows * Dc];
__device__ float g_bufX1[(size_t)Mrows * Dc];
__device__ float g_bufF[(size_t)Mrows * Fc];
__device__ int g_buckets[Bc * Hc * Sc];
__device__ int g_idx[Bc * Hc * Sc];
__device__ int g_bsort[Bc * Hc * Sc];

// ---------------- activations ----------------
enum { ACT_NONE = 0, ACT_SILU = 1, ACT_GELU = 2, ACT_SIGMOID = 3 };

template <int ACT>
__device__ __forceinline__ float apply_act(float x) {
    if (ACT == ACT_SILU) return x / (1.f + __expf(-x));
    if (ACT == ACT_GELU) {
        // JAX default gelu: tanh approximation
        float t = tanhf(0.7978845608028654f * (x + 0.044715f * x * x * x));
        return 0.5f * x * (1.f + t);
    }
    if (ACT == ACT_SIGMOID) return 1.f / (1.f + __expf(-x));
    return x;
}

// ---------------- SGEMM: C[M,N] = act(A[M,K] @ B[K,N] + bias[N]) ----------------
// BM=BN=128, BK=16, 256 threads, 8x8 per thread. M%128==0, N%128==0, K%16==0.
template <int ACT>
__global__ __launch_bounds__(256, 2) void sgemm_kernel(
    const float* __restrict__ A, const float* __restrict__ B,
    const float* __restrict__ bias, float* __restrict__ C,
    int M, int N, int K)
{
    __shared__ __align__(16) float As[16][132];  // padded, transposed A tile
    __shared__ __align__(16) float Bs[16][128];
    int tid = threadIdx.x;
    int col0 = blockIdx.x * 128;
    int row0 = blockIdx.y * 128;
    int ty = tid >> 4, tx = tid & 15;

    float acc[8][8];
#pragma unroll
    for (int i = 0; i < 8; i++)
#pragma unroll
        for (int j = 0; j < 8; j++) acc[i][j] = 0.f;

    const float* Ablk = A + (size_t)row0 * K;
    const float* Bblk = B + col0;

    for (int k0 = 0; k0 < K; k0 += 16) {
#pragma unroll
        for (int t = 0; t < 2; t++) {
            int la = tid + t * 256;
            int ar = la >> 2, ac = (la & 3) << 2;
            float4 av = *(const float4*)(Ablk + (size_t)ar * K + k0 + ac);
            As[ac + 0][ar] = av.x;
            As[ac + 1][ar] = av.y;
            As[ac + 2][ar] = av.z;
            As[ac + 3][ar] = av.w;
            int br = la >> 5, bc = (la & 31) << 2;
            *(float4*)&Bs[br][bc] = *(const float4*)(Bblk + (size_t)(k0 + br) * N + bc);
        }
        __syncthreads();
#pragma unroll
        for (int kk = 0; kk < 16; kk++) {
            float ra[8], rb[8];
            *(float4*)(ra) = *(const float4*)&As[kk][ty * 8];
            *(float4*)(ra + 4) = *(const float4*)&As[kk][ty * 8 + 4];
            *(float4*)(rb) = *(const float4*)&Bs[kk][tx * 8];
            *(float4*)(rb + 4) = *(const float4*)&Bs[kk][tx * 8 + 4];
#pragma unroll
            for (int i = 0; i < 8; i++)
#pragma unroll
                for (int j = 0; j < 8; j++) acc[i][j] += ra[i] * rb[j];
        }
        __syncthreads();
    }

#pragma unroll
    for (int i = 0; i < 8; i++) {
        size_t r = (size_t)row0 + ty * 8 + i;
#pragma unroll
        for (int j = 0; j < 8; j += 4) {
            int c = col0 + tx * 8 + j;
            float4 o;
            o.x = apply_act<ACT>(acc[i][j + 0] + bias[c + 0]);
            o.y = apply_act<ACT>(acc[i][j + 1] + bias[c + 1]);
            o.z = apply_act<ACT>(acc[i][j + 2] + bias[c + 2]);
            o.w = apply_act<ACT>(acc[i][j + 3] + bias[c + 3]);
            *(float4*)(C + r * N + c) = o;
        }
    }
}

// ---------------- time_elapsic helpers ----------------
// h = x + (shift(x) - x) * premix   (shift: zeros at s=0)
__global__ void build_h_kernel(const float* __restrict__ x,
                               const float* __restrict__ premix,
                               float* __restrict__ out)
{
    size_t i4 = (size_t)blockIdx.x * blockDim.x + threadIdx.x;
    size_t base = i4 * 4;
    int d = (int)(base & (Dc - 1));
    int row = (int)(base >> 10);
    int s = row & (Sc - 1);
    float4 xv = *(const float4*)(x + base);
    float4 pv = (s > 0) ? *(const float4*)(x + base - Dc) : make_float4(0.f, 0.f, 0.f, 0.f);
    float4 pm = *(const float4*)(premix + d);
    float4 o;
    o.x = xv.x + (pv.x - xv.x) * pm.x;
    o.y = xv.y + (pv.y - xv.y) * pm.y;
    o.z = xv.z + (pv.z - xv.z) * pm.z;
    o.w = xv.w + (pv.w - xv.w) * pm.w;
    *(float4*)(out + base) = o;
}

// out = x + (shift(x) - x) * gate
__global__ void combine_kernel(const float* __restrict__ x,
                               const float* __restrict__ gate,
                               float* __restrict__ out)
{
    size_t i4 = (size_t)blockIdx.x * blockDim.x + threadIdx.x;
    size_t base = i4 * 4;
    int row = (int)(base >> 10);
    int s = row & (Sc - 1);
    float4 xv = *(const float4*)(x + base);
    float4 pv = (s > 0) ? *(const float4*)(x + base - Dc) : make_float4(0.f, 0.f, 0.f, 0.f);
    float4 gv = *(const float4*)(gate + base);
    float4 o;
    o.x = xv.x + (pv.x - xv.x) * gv.x;
    o.y = xv.y + (pv.y - xv.y) * gv.y;
    o.z = xv.z + (pv.z - xv.z) * gv.z;
    o.w = xv.w + (pv.w - xv.w) * gv.w;
    *(float4*)(out + base) = o;
}

// ---------------- LSH hashing: buckets = argmax([k@rot, -k@rot]) ----------------
__global__ void hash_kernel(const float* __restrict__ qkv,
                            const float* __restrict__ rot,
                            int* __restrict__ buckets)
{
    int bh = blockIdx.y;
    int b = bh >> 4, h = bh & 15;
    int s = blockIdx.x * 128 + threadIdx.x;
    __shared__ float rotS[Dhc * 32];
    for (int i = threadIdx.x; i < Dhc * 32; i += 128) rotS[i] = rot[h * (Dhc * 32) + i];
    __syncthreads();
    const float* kp = qkv + ((size_t)(b * Sc + s) * QKVW) + (Hc + h) * Dhc;
    float r[32];
#pragma unroll
    for (int n = 0; n < 32; n++) r[n] = 0.f;
    for (int d = 0; d < Dhc; d++) {
        float kd = kp[d];
#pragma unroll
        for (int n = 0; n < 32; n++) r[n] += kd * rotS[d * 32 + n];
    }
    float best = r[0];
    int bi = 0;
#pragma unroll
    for (int n = 1; n < 32; n++)
        if (r[n] > best) { best = r[n]; bi = n; }
#pragma unroll
    for (int n = 0; n < 32; n++)
        if (-r[n] > best) { best = -r[n]; bi = 32 + n; }
    buckets[(size_t)bh * Sc + s] = bi;
}

// ---------------- stable counting sort per (b,h) row ----------------
__global__ void sort_kernel(const int* __restrict__ buckets,
                            int* __restrict__ idx, int* __restrict__ bsort)
{
    int bh = blockIdx.x;
    int t = threadIdx.x;  // 64 threads, one per 64-element segment
    __shared__ int sb[Sc];
    __shared__ int cnt[64][64];
    __shared__ int base[64];
    const int* row = buckets + (size_t)bh * Sc;
    for (int i = t; i < Sc; i += 64) sb[i] = row[i];
    for (int v = 0; v < 64; v++) cnt[t][v] = 0;
    __syncthreads();
    for (int i = t * 64; i < t * 64 + 64; i++) cnt[t][sb[i]]++;
    __syncthreads();
    // per-bucket prefix over segments (thread t handles bucket t)
    {
        int run = 0;
        for (int seg = 0; seg < 64; seg++) {
            int c = cnt[seg][t];
            cnt[seg][t] = run;
            run += c;
        }
        base[t] = run;  // total count for bucket t
    }
    __syncthreads();
    if (t == 0) {
        int acc = 0;
        for (int v = 0; v < 64; v++) { int c = base[v]; base[v] = acc; acc += c; }
    }
    __syncthreads();
    int* idxrow = idx + (size_t)bh * Sc;
    int* bsrow = bsort + (size_t)bh * Sc;
    for (int i = t * 64; i < t * 64 + 64; i++) {
        int v = sb[i];
        int p = base[v] + cnt[t][v]++;
        idxrow[p] = i;
        bsrow[p] = v;
    }
}

// ---------------- chunked bucket-masked attention ----------------
// block = (chunk n, b*H+h), 128 threads, one query per thread.
__global__ __launch_bounds__(128) void attn_kernel(
    const float* __restrict__ qkv, const int* __restrict__ idx,
    const int* __restrict__ bsort, float* __restrict__ yatt)
{
    int n = blockIdx.x;
    int bh = blockIdx.y;
    int b = bh >> 4, h = bh & 15;
    int tid = threadIdx.x;
    const int* idxrow = idx + (size_t)bh * Sc;
    const int* bsrow = bsort + (size_t)bh * Sc;

    int pq = n * CHUNKc + tid;
    int orig_q = idxrow[pq];
    int bq = bsrow[pq];
    const float* qptr = qkv + ((size_t)(b * Sc + orig_q) * QKVW) + h * Dhc;
    float4 qreg[16];
#pragma unroll
    for (int f = 0; f < 16; f++) qreg[f] = *(const float4*)(qptr + f * 4);

    float4 acc[16];
#pragma unroll
    for (int f = 0; f < 16; f++) acc[f] = make_float4(0.f, 0.f, 0.f, 0.f);
    float m = -1e30f, l = 0.f;

    __shared__ float4 KS[64 * 16];
    __shared__ float4 VS[64 * 16];
    __shared__ int BK[64];

    for (int tile = 0; tile < 4; tile++) {
        int t0 = tile * 64;
        for (int w = tid; w < 64 * 16; w += 128) {
            int slot = w >> 4, f = w & 15;
            int kslot = t0 + slot;
            int spos;
            bool ok;
            if (kslot < CHUNKc) { ok = (n > 0); spos = (n - 1) * CHUNKc + kslot; }
            else                { ok = true;    spos = n * CHUNKc + (kslot - CHUNKc); }
            if (ok) {
                int og = idxrow[spos];
                const float* kp = qkv + ((size_t)(b * Sc + og) * QKVW) + (Hc + h) * Dhc;
                KS[slot * 16 + f] = *(const float4*)(kp + f * 4);
                VS[slot * 16 + f] = *(const float4*)(kp + Hc * Dhc + f * 4);
                if (f == 0) BK[slot] = bsrow[spos];
            } else if (f == 0) {
                BK[slot] = -1;
            }
        }
        __syncthreads();
        for (int s = 0; s < 64; s++) {
            if (BK[s] != bq) continue;
            const float4* kp4 = &KS[s * 16];
            float dot = 0.f;
#pragma unroll
            for (int f = 0; f < 16; f++) {
                float4 kv = kp4[f];
                dot += qreg[f].x * kv.x + qreg[f].y * kv.y + qreg[f].z * kv.z + qreg[f].w * kv.w;
            }
            dot *= 0.125f;  // 1/sqrt(64)
            float p;
            if (dot > m) {
                float sc = __expf(m - dot);
                l *= sc;
#pragma unroll
                for (int f = 0; f < 16; f++) {
                    acc[f].x *= sc; acc[f].y *= sc; acc[f].z *= sc; acc[f].w *= sc;
                }
                m = dot;
                p = 1.f;
            } else {
                p = __expf(dot - m);
            }
            l += p;
            const float4* vp4 = &VS[s * 16];
#pragma unroll
            for (int f = 0; f < 16; f++) {
                float4 vv = vp4[f];
                acc[f].x += p * vv.x; acc[f].y += p * vv.y;
                acc[f].z += p * vv.z; acc[f].w += p * vv.w;
            }
        }
        __syncthreads();
    }
    float inv = 1.f / l;
    float* yp = yatt + ((size_t)(b * Sc + orig_q)) * Dc + h * Dhc;  // scatter = unsort
#pragma unroll
    for (int f = 0; f < 16; f++) {
        float4 o = acc[f];
        o.x *= inv; o.y *= inv; o.z *= inv; o.w *= inv;
        *(float4*)(yp + f * 4) = o;
    }
}

// ---------------- LayerNorm(a + b) ----------------
__global__ void ln_add_kernel(const float* __restrict__ a, const float* __restrict__ bsum,
                              const float* __restrict__ g, const float* __restrict__ be,
                              float* __restrict__ out)
{
    int r = blockIdx.x, tid = threadIdx.x;
    size_t base = (size_t)r * Dc + tid * 4;
    float4 av = *(const float4*)(a + base);
    float4 bv = *(const float4*)(bsum + base);
    float4 v = make_float4(av.x + bv.x, av.y + bv.y, av.z + bv.z, av.w + bv.w);
    float s = v.x + v.y + v.z + v.w;
    float s2 = v.x * v.x + v.y * v.y + v.z * v.z + v.w * v.w;
    for (int o = 16; o > 0; o >>= 1) {
        s += __shfl_down_sync(~0u, s, o);
        s2 += __shfl_down_sync(~0u, s2, o);
    }
    __shared__ float ws[8], ws2[8];
    __shared__ float mean_s, rstd_s;
    int w = tid >> 5, ln = tid & 31;
    if (ln == 0) { ws[w] = s; ws2[w] = s2; }
    __syncthreads();
    if (tid == 0) {
        float S = 0.f, S2 = 0.f;
        for (int i = 0; i < 8; i++) { S += ws[i]; S2 += ws2[i]; }
        float mean = S * (1.f / Dc);
        float var = S2 * (1.f / Dc) - mean * mean;
        mean_s = mean;
        rstd_s = rsqrtf(var + 1e-5f);
    }
    __syncthreads();
    float mean = mean_s, rstd = rstd_s;
    float4 gv = *(const float4*)(g + tid * 4);
    float4 bev = *(const float4*)(be + tid * 4);
    float4 o;
    o.x = (v.x - mean) * rstd * gv.x + bev.x;
    o.y = (v.y - mean) * rstd * gv.y + bev.y;
    o.z = (v.z - mean) * rstd * gv.z + bev.z;
    o.w = (v.w - mean) * rstd * gv.w + bev.w;
    *(float4*)(out + base) = o;
}

// ---------------- LayerNorm(x1 + t * emb[ph]) ----------------
__global__ void ln_emb_kernel(const float* __restrict__ x1, const float* __restrict__ tin,
                              const float* __restrict__ emb, const int* __restrict__ ph,
                              const float* __restrict__ g, const float* __restrict__ be,
                              float* __restrict__ out)
{
    int r = blockIdx.x, tid = threadIdx.x;
    size_t base = (size_t)r * Dc + tid * 4;
    const float* er = emb + (size_t)ph[r] * Dc;
    float4 av = *(const float4*)(x1 + base);
    float4 tv = *(const float4*)(tin + base);
    float4 ev = *(const float4*)(er + tid * 4);
    float4 v = make_float4(av.x + tv.x * ev.x, av.y + tv.y * ev.y,
                           av.z + tv.z * ev.z, av.w + tv.w * ev.w);
    float s = v.x + v.y + v.z + v.w;
    float s2 = v.x * v.x + v.y * v.y + v.z * v.z + v.w * v.w;
    for (int o = 16; o > 0; o >>= 1) {
        s += __shfl_down_sync(~0u, s, o);
        s2 += __shfl_down_sync(~0u, s2, o);
    }
    __shared__ float ws[8], ws2[8];
    __shared__ float mean_s, rstd_s;
    int w = tid >> 5, ln = tid & 31;
    if (ln == 0) { ws[w] = s; ws2[w] = s2; }
    __syncthreads();
    if (tid == 0) {
        float S = 0.f, S2 = 0.f;
        for (int i = 0; i < 8; i++) { S += ws[i]; S2 += ws2[i]; }
        float mean = S * (1.f / Dc);
        float var = S2 * (1.f / Dc) - mean * mean;
        mean_s = mean;
        rstd_s = rsqrtf(var + 1e-5f);
    }
    __syncthreads();
    float mean = mean_s, rstd = rstd_s;
    float4 gv = *(const float4*)(g + tid * 4);
    float4 bev = *(const float4*)(be + tid * 4);
    float4 o;
    o.x = (v.x - mean) * rstd * gv.x + bev.x;
    o.y = (v.y - mean) * rstd * gv.y + bev.y;
    o.z = (v.z - mean) * rstd * gv.z + bev.z;
    o.w = (v.w - mean) * rstd * gv.w + bev.w;
    *(float4*)(out + base) = o;
}

// ---------------- launch ----------------
extern "C" void kernel_launch(void* const* d_in, const int* in_sizes, int n_in,
                              void* d_out, int out_size)
{
    const float* x       = (const float*)d_in[0];
    const float* premix1 = (const float*)d_in[1];
    const float* e1w1    = (const float*)d_in[2];
    const float* e1b1    = (const float*)d_in[3];
    const float* e1w2    = (const float*)d_in[4];
    const float* e1b2    = (const float*)d_in[5];
    const float* premix2 = (const float*)d_in[6];
    const float* e2w1    = (const float*)d_in[7];
    const float* e2b1    = (const float*)d_in[8];
    const float* e2w2    = (const float*)d_in[9];
    const float* e2b2    = (const float*)d_in[10];
    const float* wqkv    = (const float*)d_in[11];
    const float* bqkv    = (const float*)d_in[12];
    const float* wo      = (const float*)d_in[13];
    const float* bo      = (const float*)d_in[14];
    const float* rot     = (const float*)d_in[15];
    const float* ln1g    = (const float*)d_in[16];
    const float* ln1b    = (const float*)d_in[17];
    const float* ln2g    = (const float*)d_in[18];
    const float* ln2b    = (const float*)d_in[19];
    const float* emb     = (const float*)d_in[20];
    const float* mw1     = (const float*)d_in[21];
    const float* mb1     = (const float*)d_in[22];
    const float* mw2     = (const float*)d_in[23];
    const float* mb2     = (const float*)d_in[24];
    const int*   ph      = (const int*)d_in[25];
    float* out = (float*)d_out;

    float *pH, *pE, *pG, *pXA, *pQKV, *pATT, *pT, *pX1, *pF;
    int *pBk, *pIdx, *pBs;
    cudaGetSymbolAddress((void**)&pH, g_bufH);
    cudaGetSymbolAddress((void**)&pE, g_bufE);
    cudaGetSymbolAddress((void**)&pG, g_bufG);
    cudaGetSymbolAddress((void**)&pXA, g_bufXA);
    cudaGetSymbolAddress((void**)&pQKV, g_bufQKV);
    cudaGetSymbolAddress((void**)&pATT, g_bufATT);
    cudaGetSymbolAddress((void**)&pT, g_bufT);
    cudaGetSymbolAddress((void**)&pX1, g_bufX1);
    cudaGetSymbolAddress((void**)&pF, g_bufF);
    cudaGetSymbolAddress((void**)&pBk, g_buckets);
    cudaGetSymbolAddress((void**)&pIdx, g_idx);
    cudaGetSymbolAddress((void**)&pBs, g_bsort);

    const int ew_blocks = Mrows * Dc / (256 * 4);  // 16384

    // ---- time_elapsic 1 (input x) ----
    build_h_kernel<<<ew_blocks, 256>>>(x, premix1, pH);
    sgemm_kernel<ACT_SILU><<<dim3(Ec / 128, Mrows / 128), 256>>>(pH, e1w1, e1b1, pE, Mrows, Ec, Dc);
    sgemm_kernel<ACT_SIGMOID><<<dim3(Dc / 128, Mrows / 128), 256>>>(pE, e1w2, e1b2, pG, Mrows, Dc, Ec);
    combine_kernel<<<ew_blocks, 256>>>(x, pG, pXA);

    // ---- LSH attention ----
    sgemm_kernel<ACT_NONE><<<dim3(QKVW / 128, Mrows / 128), 256>>>(pXA, wqkv, bqkv, pQKV, Mrows, QKVW, Dc);
    hash_kernel<<<dim3(Sc / 128, Bc * Hc), 128>>>(pQKV, rot, pBk);
    sort_kernel<<<Bc * Hc, 64>>>(pBk, pIdx, pBs);
    attn_kernel<<<dim3(NCHUNK, Bc * Hc), 128>>>(pQKV, pIdx, pBs, pATT);
    sgemm_kernel<ACT_NONE><<<dim3(Dc / 128, Mrows / 128), 256>>>(pATT, wo, bo, pT, Mrows, Dc, Dc);
    ln_add_kernel<<<Mrows, 256>>>(x, pT, ln1g, ln1b, pX1);

    // ---- time_elapsic 2 (input x1) ----
    build_h_kernel<<<ew_blocks, 256>>>(pX1, premix2, pH);
    sgemm_kernel<ACT_SILU><<<dim3(Ec / 128, Mrows / 128), 256>>>(pH, e2w1, e2b1, pE, Mrows, Ec, Dc);
    sgemm_kernel<ACT_SIGMOID><<<dim3(Dc / 128, Mrows / 128), 256>>>(pE, e2w2, e2b2, pG, Mrows, Dc, Ec);
    combine_kernel<<<ew_blocks, 256>>>(pX1, pG, pXA);

    // ---- MLP + deepembed + LN2 ----
    sgemm_kernel<ACT_GELU><<<dim3(Fc / 128, Mrows / 128), 256>>>(pXA, mw1, mb1, pF, Mrows, Fc, Dc);
    sgemm_kernel<ACT_NONE><<<dim3(Dc / 128, Mrows / 128), 256>>>(pF, mw2, mb2, pT, Mrows, Dc, Fc);
    ln_emb_kernel<<<Mrows, 256>>>(pX1, pT, emb, ph, ln2g, ln2b, out);
}